// round 9
// baseline (speedup 1.0000x reference)
#include <cuda_runtime.h>
#include <cuda_fp16.h>
#include <cstdint>

typedef unsigned long long ull;

// ---------------- problem constants ----------------
#define N_IMG   32
#define C_IN    256
#define HW      64
#define K_OUT   256
#define X_ELEMS (N_IMG * C_IN * HW * HW)          // 33554432
#define W_ELEMS (K_OUT * C_IN * 9)                // 589824
#define NWBLK   (W_ELEMS / 16)                    // 36864
#define NTILE   32
#define TILES_PER_IMG (NTILE * NTILE)             // 1024
#define DT_POS_STRIDE ((size_t)N_IMG * TILES_PER_IMG * C_IN)   // 8388608

// ---------------- scratch ----------------
__device__ uint8_t g_xq[X_ELEMS];                     // NHWC fp8 (exact quantized)
__device__ uint8_t g_wq2[9 * K_OUT * C_IN];           // [rs][k][c] fp8 (exact)
__device__ __half  g_gt[16 * K_OUT * C_IN];           // winograd weights fp16
__device__ __half  g_dt[16ull * N_IMG * TILES_PER_IMG * C_IN]; // winograd data fp16

// ---------------- fp8 helpers ----------------
__device__ __forceinline__ uint16_t pack_e4m3_x2(float lo, float hi) {
    uint16_t r;
    asm volatile("cvt.rn.satfinite.e4m3x2.f32 %0, %1, %2;" : "=h"(r) : "f"(hi), "f"(lo));
    return r;
}
__device__ __forceinline__ uint8_t f32_to_e4m3(float v) {
    uint16_t r;
    asm volatile("cvt.rn.satfinite.e4m3x2.f32 %0, %1, %2;" : "=h"(r) : "f"(0.0f), "f"(v));
    return (uint8_t)(r & 0xFF);
}
__device__ __forceinline__ float e4m3_to_f32(uint8_t b) {
    uint16_t s = b;
    uint32_t h2;
    asm("cvt.rn.f16x2.e4m3x2 %0, %1;" : "=r"(h2) : "h"(s));
    __half lo = __ushort_as_half((uint16_t)(h2 & 0xFFFF));
    return __half2float(lo);
}

// ---------------- fake-quant core (exact pow2 scale + RTN E2M1) ----------------
__device__ __forceinline__ void quant16f(const float* __restrict__ v,
                                         float* __restrict__ q) {
    float amax = 0.0f;
#pragma unroll
    for (int i = 0; i < 16; ++i) amax = fmaxf(amax, fabsf(v[i]));
    float scale = 1.0f;
    if (amax > 0.0f) {
        float y = fmaxf(amax, 1e-30f) / 6.0f;
        int e;
        float m = frexpf(y, &e);
        scale = ldexpf(1.0f, (m == 0.5f) ? (e - 1) : e);
    }
    float inv = 1.0f / scale;
#pragma unroll
    for (int i = 0; i < 16; ++i) {
        float u = v[i] * inv;
        float a = fabsf(u);
        float g;
        if      (a < 0.25f) g = 0.0f;
        else if (a < 0.75f) g = 0.5f;
        else if (a < 1.25f) g = 1.0f;
        else if (a < 1.75f) g = 1.5f;
        else if (a < 2.5f)  g = 2.0f;
        else if (a < 3.5f)  g = 3.0f;
        else if (a < 5.0f)  g = 4.0f;
        else                g = 6.0f;
        q[i] = copysignf(g, u) * scale;     // exact in e4m3
    }
}

// ---------------- x quant -> NHWC fp8 (proven) ----------------
__global__ void __launch_bounds__(256)
quant_x_nhwc(const float* __restrict__ x, uint8_t* __restrict__ xq) {
    __shared__ uint16_t buf[64][136];
    const int n = blockIdx.x;
    const int h = blockIdx.y;
    const int t = threadIdx.x;
    const int cp  = t & 127;
    const int wb0 = t >> 7;

#pragma unroll
    for (int wbi = 0; wbi < 2; ++wbi) {
        int wb = wb0 + wbi * 2;
        const float* base = x + (((size_t)n * C_IN + 2 * cp) * HW + h) * HW + wb * 16;
        const float4* p0 = reinterpret_cast<const float4*>(base);
        const float4* p1 = reinterpret_cast<const float4*>(base + (size_t)HW * HW);
        float v0[16], v1[16];
#pragma unroll
        for (int i = 0; i < 4; ++i) {
            float4 a = p0[i];
            v0[i * 4 + 0] = a.x; v0[i * 4 + 1] = a.y; v0[i * 4 + 2] = a.z; v0[i * 4 + 3] = a.w;
            float4 b = p1[i];
            v1[i * 4 + 0] = b.x; v1[i * 4 + 1] = b.y; v1[i * 4 + 2] = b.z; v1[i * 4 + 3] = b.w;
        }
        float q0[16], q1[16];
        quant16f(v0, q0);
        quant16f(v1, q1);
#pragma unroll
        for (int j = 0; j < 16; ++j)
            buf[wb * 16 + j][cp] = pack_e4m3_x2(q0[j], q1[j]);
    }
    __syncthreads();

    uint8_t* orow = xq + (((size_t)n * HW + h) * HW) * C_IN;
#pragma unroll
    for (int i = 0; i < 4; ++i) {
        int idx = t + 256 * i;
        int p   = idx >> 4;
        int qd  = idx & 15;
        uint4 val = *reinterpret_cast<const uint4*>(&buf[p][qd * 8]);
        *reinterpret_cast<uint4*>(orow + (size_t)p * C_IN + qd * 16) = val;
    }
}

// ---------------- w quant + repack -> [rs][k][c] fp8 (proven) ----------------
__global__ void quant_w_repack(const float* __restrict__ w,
                               uint8_t* __restrict__ wq2) {
    int b = blockIdx.x * blockDim.x + threadIdx.x;
    if (b >= NWBLK) return;
    const float4* src = reinterpret_cast<const float4*>(w) + (size_t)b * 4;
    float4 t0 = src[0], t1 = src[1], t2 = src[2], t3 = src[3];
    float v[16] = {t0.x, t0.y, t0.z, t0.w, t1.x, t1.y, t1.z, t1.w,
                   t2.x, t2.y, t2.z, t2.w, t3.x, t3.y, t3.z, t3.w};
    float q[16];
    quant16f(v, q);
#pragma unroll
    for (int i = 0; i < 16; ++i) {
        int f  = b * 16 + i;
        int k  = f / 2304;
        int r2 = f - k * 2304;
        int c  = r2 / 9;
        int rs = r2 - c * 9;
        wq2[((size_t)rs * K_OUT + k) * C_IN + c] = f32_to_e4m3(q[i]);
    }
}

// ---------------- winograd weight transform (proven) ----------------
__global__ void __launch_bounds__(256)
wg_transform(const uint8_t* __restrict__ wq2, __half* __restrict__ gt) {
    int k = blockIdx.x;
    int c = threadIdx.x;
    float w9[9];
#pragma unroll
    for (int rs = 0; rs < 9; ++rs)
        w9[rs] = e4m3_to_f32(wq2[((size_t)rs * K_OUT + k) * C_IN + c]);
    float a[4][3];
#pragma unroll
    for (int j = 0; j < 3; ++j) {
        float w0 = w9[0 * 3 + j], w1 = w9[1 * 3 + j], w2 = w9[2 * 3 + j];
        a[0][j] = w0;
        a[1][j] = 0.5f * (w0 + w1 + w2);
        a[2][j] = 0.5f * (w0 - w1 + w2);
        a[3][j] = w2;
    }
#pragma unroll
    for (int i = 0; i < 4; ++i) {
        float u0 = a[i][0], u1 = a[i][1], u2 = a[i][2];
        float u[4] = {u0, 0.5f * (u0 + u1 + u2), 0.5f * (u0 - u1 + u2), u2};
#pragma unroll
        for (int j = 0; j < 4; ++j)
            gt[((size_t)(i * 4 + j) * K_OUT + k) * C_IN + c] = __float2half(u[j]);
    }
}

// ---------------- cp.async helpers ----------------
__device__ __forceinline__ void cp_async16(void* dst, const void* src, bool pred) {
    uint32_t d = (uint32_t)__cvta_generic_to_shared(dst);
    int sz = pred ? 16 : 0;
    asm volatile("cp.async.cg.shared.global [%0], [%1], 16, %2;\n"
                 :: "r"(d), "l"(src), "r"(sz));
}
__device__ __forceinline__ void cp_commit() {
    asm volatile("cp.async.commit_group;\n");
}
template <int N>
__device__ __forceinline__ void cp_wait() {
    asm volatile("cp.async.wait_group %0;\n" :: "n"(N));
}

// ---------------- winograd data transform (proven, 46us) ----------------
__global__ void __launch_bounds__(256)
dt_transform(const uint8_t* __restrict__ xq, __half* __restrict__ dt) {
    extern __shared__ uint8_t sx[];
    const int n  = blockIdx.x;
    const int th = blockIdx.y;
    const int t  = threadIdx.x;

#pragma unroll
    for (int i = 0; i < 16; ++i) {
        int idx = t + 256 * i;
        int h1  = idx >> 10;
        int rem = idx & 1023;
        int w   = rem >> 4;
        int cq  = rem & 15;
        int gh  = th * 2 - 1 + h1;
        bool ok = (unsigned)gh < (unsigned)HW;
        cp_async16(sx + ((size_t)h1 * 64 + w) * 256 + cq * 16,
                   xq + (((size_t)n * HW + (ok ? gh : 0)) * HW + w) * C_IN + cq * 16, ok);
    }
    cp_commit();
    cp_wait<0>();
    __syncthreads();

    const int cp  = t & 127;
    const int twh = t >> 7;
    const __half2 zero = __floats2half2_rn(0.f, 0.f);

#pragma unroll 1
    for (int j = 0; j < 16; ++j) {
        int tw = j * 2 + twh;
        __half2 d[4][4];
#pragma unroll
        for (int wi = 0; wi < 4; ++wi) {
            int w = 2 * tw - 1 + wi;
            bool ok = (unsigned)w < (unsigned)HW;
#pragma unroll
            for (int h1 = 0; h1 < 4; ++h1) {
                if (ok) {
                    uint16_t u = *reinterpret_cast<const uint16_t*>(
                        sx + ((size_t)h1 * 64 + w) * 256 + 2 * cp);
                    uint32_t h2;
                    asm("cvt.rn.f16x2.e4m3x2 %0, %1;" : "=r"(h2) : "h"(u));
                    d[h1][wi] = *reinterpret_cast<__half2*>(&h2);
                } else {
                    d[h1][wi] = zero;
                }
            }
        }
        __half2 e[4][4];
#pragma unroll
        for (int h1 = 0; h1 < 4; ++h1) {
            e[h1][0] = __hsub2(d[h1][0], d[h1][2]);
            e[h1][1] = __hadd2(d[h1][1], d[h1][2]);
            e[h1][2] = __hsub2(d[h1][2], d[h1][1]);
            e[h1][3] = __hsub2(d[h1][1], d[h1][3]);
        }
        size_t tb = ((size_t)n * TILES_PER_IMG + th * NTILE + tw) * C_IN + 2 * cp;
#pragma unroll
        for (int jj = 0; jj < 4; ++jj) {
            __half2 D[4];
            D[0] = __hsub2(e[0][jj], e[2][jj]);
            D[1] = __hadd2(e[1][jj], e[2][jj]);
            D[2] = __hsub2(e[2][jj], e[1][jj]);
            D[3] = __hsub2(e[1][jj], e[3][jj]);
#pragma unroll
            for (int ii = 0; ii < 4; ++ii)
                *reinterpret_cast<uint32_t*>(&dt[(size_t)(ii * 4 + jj) * DT_POS_STRIDE + tb]) =
                    *reinterpret_cast<uint32_t*>(&D[ii]);
        }
    }
}

// ---------------- ldsm / mma / f32x2 ----------------
__device__ __forceinline__ void ldsm_x4(uint32_t addr, uint32_t& r0, uint32_t& r1,
                                        uint32_t& r2, uint32_t& r3) {
    asm volatile("ldmatrix.sync.aligned.m8n8.x4.shared.b16 {%0,%1,%2,%3}, [%4];"
                 : "=r"(r0), "=r"(r1), "=r"(r2), "=r"(r3) : "r"(addr));
}
__device__ __forceinline__ void mma16816f16(float* d, const uint32_t* a,
                                            uint32_t b0, uint32_t b1) {
    asm volatile("mma.sync.aligned.m16n8k16.row.col.f32.f16.f16.f32 "
                 "{%0,%1,%2,%3}, {%4,%5,%6,%7}, {%8,%9}, {%0,%1,%2,%3};"
                 : "+f"(d[0]), "+f"(d[1]), "+f"(d[2]), "+f"(d[3])
                 : "r"(a[0]), "r"(a[1]), "r"(a[2]), "r"(a[3]), "r"(b0), "r"(b1));
}
__device__ __forceinline__ ull pack2(float lo, float hi) {
    ull r;
    asm("mov.b64 %0, {%1, %2};" : "=l"(r) : "f"(lo), "f"(hi));
    return r;
}
__device__ __forceinline__ void p2add(ull& y, ull m) {
    asm("add.rn.f32x2 %0, %0, %1;" : "+l"(y) : "l"(m));
}
__device__ __forceinline__ void p2sub(ull& y, ull m, ull neg1) {
    asm("fma.rn.f32x2 %0, %1, %2, %0;" : "+l"(y) : "l"(m), "l"(neg1));
}

// ---------------- winograd GEMM v2: fused incremental inverse ----------------
// CTA: 64k x 64tiles x 16pos, 512 threads (16 warps = 4 wk x 4 wt).
// Warp tile per pos: 16k x 16tw (2 LDSM.x4 -> 2 MMA). Incremental A^T M A fold.
#define GA_ROWS 1024                          // 16 pos x 64 k
#define GB_ROWS 1024                          // 16 pos x 64 tiles
#define GSTAGE  ((GA_ROWS + GB_ROWS) * 48)    // 98304
#define GSMEM   (2 * GSTAGE)                  // 196608

__device__ __forceinline__ void gemm_stage(char* base,
                                           const __half* __restrict__ gt,
                                           const __half* __restrict__ dt,
                                           int k0, size_t tb0, int cc, int t) {
#pragma unroll
    for (int i = 0; i < 8; ++i) {
        int idx  = t + 512 * i;              // 0..4095
        int rid  = idx >> 1;
        int half = idx & 1;
        const void* src;
        if (rid < GA_ROWS) {
            int pos = rid >> 6;
            int kk  = rid & 63;
            src = gt + ((size_t)pos * K_OUT + k0 + kk) * C_IN + cc + half * 8;
        } else {
            int r2  = rid - GA_ROWS;
            int pos = r2 >> 6;
            int twi = r2 & 63;               // thh*32 + tw
            src = dt + (size_t)pos * DT_POS_STRIDE + tb0 + (size_t)twi * C_IN
                     + cc + half * 8;
        }
        cp_async16(base + rid * 48 + half * 16, src, true);
    }
}

__global__ void __launch_bounds__(512, 1)
wino_gemm(const __half* __restrict__ gt, const __half* __restrict__ dt,
          float* __restrict__ out) {
    extern __shared__ char smem[];
    const int kt = blockIdx.x;               // 0..3 (fastest -> B shared in L2)
    const int tg = blockIdx.y;               // 0..15 (pair of tile rows)
    const int n  = blockIdx.z;
    const int k0 = kt * 64;
    const int th0 = tg * 2;

    const int t    = threadIdx.x;
    const int lane = t & 31;
    const int warp = t >> 5;
    const int wk   = warp & 3;               // k group of 16
    const int wt   = warp >> 2;              // tile group of 16

    // tile base: tiles (th0..th0+1) x 32 cols, flattened consecutively (64 rows)
    const size_t tb0 = ((size_t)n * TILES_PER_IMG + th0 * NTILE) * C_IN;

    const ull NEG1 = 0xBF800000BF800000ULL;

    // y[a][b][slot]: slot = kr*1... slots: 0=(kr0,nt0) 1=(kr1,nt0) 2=(kr0,nt1) 3=(kr1,nt1)
    ull y[2][2][4];
#pragma unroll
    for (int a = 0; a < 2; ++a)
#pragma unroll
        for (int b = 0; b < 2; ++b)
#pragma unroll
            for (int s = 0; s < 4; ++s) y[a][b][s] = 0ull;

    gemm_stage(smem, gt, dt, k0, tb0, 0, t);
    cp_commit();

    const uint32_t su = (uint32_t)__cvta_generic_to_shared(smem);
    const int a_off = (lane & 15) * 48 + (lane >> 4) * 16;
    const int b_off = ((lane & 7) + (lane >> 4) * 8) * 48 + ((lane >> 3) & 1) * 16;

#pragma unroll 1
    for (int it = 0; it < 16; ++it) {
        const int cur = it & 1;
        if (it + 1 < 16) {
            gemm_stage(smem + (cur ^ 1) * GSTAGE, gt, dt, k0, tb0, (it + 1) * 16, t);
            cp_commit();
            cp_wait<1>();
        } else {
            cp_wait<0>();
        }
        __syncthreads();

        const uint32_t sA = su + cur * GSTAGE;
        const uint32_t sB = sA + GA_ROWS * 48;

#pragma unroll
        for (int i4 = 0; i4 < 4; ++i4) {
            ull z[2][4];
#pragma unroll
            for (int j = 0; j < 4; ++j) {
                const int pos = i4 * 4 + j;
                uint32_t a[4], b[4];
                ldsm_x4(sA + (pos * 64 + wk * 16) * 48 + a_off, a[0], a[1], a[2], a[3]);
                ldsm_x4(sB + (pos * 64 + wt * 16) * 48 + b_off, b[0], b[1], b[2], b[3]);
                float m[8];
#pragma unroll
                for (int v = 0; v < 8; ++v) m[v] = 0.0f;
                mma16816f16(m + 0, a, b[0], b[1]);
                mma16816f16(m + 4, a, b[2], b[3]);
                ull mp[4];
                mp[0] = pack2(m[0], m[1]);   // (kr0, nt0)
                mp[1] = pack2(m[2], m[3]);   // (kr1, nt0)
                mp[2] = pack2(m[4], m[5]);   // (kr0, nt1)
                mp[3] = pack2(m[6], m[7]);   // (kr1, nt1)
                // z[b] += A^T[b][j] * m   (A^T = [[1,1,1,0],[0,1,-1,-1]])
                if (j == 0) {
#pragma unroll
                    for (int s = 0; s < 4; ++s) z[0][s] = mp[s];
                } else if (j == 1) {
#pragma unroll
                    for (int s = 0; s < 4; ++s) { p2add(z[0][s], mp[s]); z[1][s] = mp[s]; }
                } else if (j == 2) {
#pragma unroll
                    for (int s = 0; s < 4; ++s) { p2add(z[0][s], mp[s]); p2sub(z[1][s], mp[s], NEG1); }
                } else {
#pragma unroll
                    for (int s = 0; s < 4; ++s) p2sub(z[1][s], mp[s], NEG1);
                }
            }
            // y[a] += A^T[a][i4] * z
            if (i4 == 0) {
#pragma unroll
                for (int b = 0; b < 2; ++b)
#pragma unroll
                    for (int s = 0; s < 4; ++s) p2add(y[0][b][s], z[b][s]);
            } else if (i4 == 1) {
#pragma unroll
                for (int b = 0; b < 2; ++b)
#pragma unroll
                    for (int s = 0; s < 4; ++s) { p2add(y[0][b][s], z[b][s]); p2add(y[1][b][s], z[b][s]); }
            } else if (i4 == 2) {
#pragma unroll
                for (int b = 0; b < 2; ++b)
#pragma unroll
                    for (int s = 0; s < 4; ++s) { p2add(y[0][b][s], z[b][s]); p2sub(y[1][b][s], z[b][s], NEG1); }
            } else {
#pragma unroll
                for (int b = 0; b < 2; ++b)
#pragma unroll
                    for (int s = 0; s < 4; ++s) p2sub(y[1][b][s], z[b][s], NEG1);
            }
        }
        __syncthreads();
    }

    // ---- epilogue ----
    const int g  = lane >> 2;
    const int tc = lane & 3;
#pragma unroll
    for (int kr = 0; kr < 2; ++kr) {
        const int k = k0 + wk * 16 + g + kr * 8;
#pragma unroll
        for (int nt = 0; nt < 2; ++nt) {
            const int twi = wt * 16 + nt * 8 + 2 * tc;   // first of the pair
            const int thh = twi >> 5;
            const int twc = twi & 31;
            const int s = kr + nt * 2;
#pragma unroll
            for (int a = 0; a < 2; ++a) {
                float l0, h0, l1, h1;
                asm("mov.b64 {%0, %1}, %2;" : "=f"(l0), "=f"(h0) : "l"(y[a][0][s]));
                asm("mov.b64 {%0, %1}, %2;" : "=f"(l1), "=f"(h1) : "l"(y[a][1][s]));
                // w order: (tw0,b0),(tw0,b1),(tw1,b0),(tw1,b1)
                float4 v = make_float4(l0, l1, h0, h1);
                size_t o = (((size_t)n * K_OUT + k) * HW + 2 * (th0 + thh) + a) * HW
                         + 2 * twc;
                *reinterpret_cast<float4*>(out + o) = v;
            }
        }
    }
}

// ---------------- launch ----------------
extern "C" void kernel_launch(void* const* d_in, const int* in_sizes, int n_in,
                              void* d_out, int out_size) {
    const float* x = (const float*)d_in[0];
    const float* w = (const float*)d_in[1];
    if (in_sizes[0] != X_ELEMS) {
        x = (const float*)d_in[1];
        w = (const float*)d_in[0];
    }

    void *xq_p, *wq_p, *gt_p, *dt_p;
    cudaGetSymbolAddress(&xq_p, g_xq);
    cudaGetSymbolAddress(&wq_p, g_wq2);
    cudaGetSymbolAddress(&gt_p, g_gt);
    cudaGetSymbolAddress(&dt_p, g_dt);
    uint8_t* xq  = (uint8_t*)xq_p;
    uint8_t* wq2 = (uint8_t*)wq_p;
    __half*  gt  = (__half*)gt_p;
    __half*  dt  = (__half*)dt_p;

    cudaFuncSetAttribute(dt_transform,
                         cudaFuncAttributeMaxDynamicSharedMemorySize, 65536);
    cudaFuncSetAttribute(wino_gemm,
                         cudaFuncAttributeMaxDynamicSharedMemorySize, GSMEM);

    quant_x_nhwc<<<dim3(N_IMG, HW), 256>>>(x, xq);
    quant_w_repack<<<(NWBLK + 255) / 256, 256>>>(w, wq2);
    wg_transform<<<K_OUT, C_IN>>>(wq2, gt);
    dt_transform<<<dim3(N_IMG, NTILE), 256, 65536>>>(xq, dt);
    wino_gemm<<<dim3(4, 16, N_IMG), 512, GSMEM>>>(gt, dt, (float*)d_out);
}

// round 10
// speedup vs baseline: 2.1080x; 2.1080x over previous
#include <cuda_runtime.h>
#include <cuda_fp16.h>
#include <cstdint>

// ---------------- problem constants ----------------
#define N_IMG   32
#define C_IN    256
#define HW      64
#define K_OUT   256
#define X_ELEMS (N_IMG * C_IN * HW * HW)          // 33554432
#define W_ELEMS (K_OUT * C_IN * 9)                // 589824
#define NWBLK   (W_ELEMS / 16)                    // 36864

// ---------------- scratch (fp16 quantized tensors) ----------------
__device__ __half g_xq[X_ELEMS];                  // NHWC: ((n*64+h)*64+w)*256 + c
__device__ __half g_wq2[9 * K_OUT * C_IN];        // [rs][k][c]

// ---------------- fake-quant core (exact pow2 scale + RTN E2M1) ----------------
__device__ __forceinline__ void quant16f(const float* __restrict__ v,
                                         float* __restrict__ q) {
    float amax = 0.0f;
#pragma unroll
    for (int i = 0; i < 16; ++i) amax = fmaxf(amax, fabsf(v[i]));
    float scale = 1.0f;
    if (amax > 0.0f) {
        float y = fmaxf(amax, 1e-30f) / 6.0f;
        int e;
        float m = frexpf(y, &e);                            // y = m*2^e, m in [0.5,1)
        scale = ldexpf(1.0f, (m == 0.5f) ? (e - 1) : e);    // exact ceil(log2 y)
    }
    float inv = 1.0f / scale;
#pragma unroll
    for (int i = 0; i < 16; ++i) {
        float u = v[i] * inv;
        float a = fabsf(u);
        float g;
        if      (a < 0.25f) g = 0.0f;
        else if (a < 0.75f) g = 0.5f;
        else if (a < 1.25f) g = 1.0f;
        else if (a < 1.75f) g = 1.5f;
        else if (a < 2.5f)  g = 2.0f;
        else if (a < 3.5f)  g = 3.0f;
        else if (a < 5.0f)  g = 4.0f;
        else                g = 6.0f;
        q[i] = copysignf(g, u) * scale;                     // exact in fp16
    }
}

// ---------------- x quant -> NHWC fp16 (round-3 proven, 53.6us) ----------------
__global__ void __launch_bounds__(256)
quant_x_nhwc(const float* __restrict__ x, __half* __restrict__ xq) {
    __shared__ uint32_t buf[64][132];    // [pixel][cpair] packed half2
    const int n = blockIdx.x;
    const int h = blockIdx.y;
    const int t = threadIdx.x;
    const int cp  = t & 127;             // channel pair: c = 2cp, 2cp+1
    const int wb0 = t >> 7;

#pragma unroll
    for (int wbi = 0; wbi < 2; ++wbi) {
        int wb = wb0 + wbi * 2;
        const float* base = x + (((size_t)n * C_IN + 2 * cp) * HW + h) * HW + wb * 16;
        const float4* p0 = reinterpret_cast<const float4*>(base);
        const float4* p1 = reinterpret_cast<const float4*>(base + (size_t)HW * HW);
        float v0[16], v1[16];
#pragma unroll
        for (int i = 0; i < 4; ++i) {
            float4 a = p0[i];
            v0[i * 4 + 0] = a.x; v0[i * 4 + 1] = a.y; v0[i * 4 + 2] = a.z; v0[i * 4 + 3] = a.w;
            float4 b = p1[i];
            v1[i * 4 + 0] = b.x; v1[i * 4 + 1] = b.y; v1[i * 4 + 2] = b.z; v1[i * 4 + 3] = b.w;
        }
        float q0[16], q1[16];
        quant16f(v0, q0);
        quant16f(v1, q1);
#pragma unroll
        for (int j = 0; j < 16; ++j) {
            __half2 pk = __floats2half2_rn(q0[j], q1[j]);   // exact values
            buf[wb * 16 + j][cp] = *reinterpret_cast<uint32_t*>(&pk);
        }
    }
    __syncthreads();

#pragma unroll
    for (int i = 0; i < 8; ++i) {
        int idx = t + 256 * i;
        int p   = idx >> 5;
        int q   = idx & 31;
        uint4 val = *reinterpret_cast<const uint4*>(&buf[p][q * 4]);
        uint4* dst = reinterpret_cast<uint4*>(
            xq + (((size_t)n * HW + h) * HW + p) * C_IN);
        dst[q] = val;
    }
}

// ---------------- w quant + repack -> [rs][k][c] fp16 ----------------
__global__ void quant_w_repack(const float* __restrict__ w,
                               __half* __restrict__ wq2) {
    int b = blockIdx.x * blockDim.x + threadIdx.x;
    if (b >= NWBLK) return;
    const float4* src = reinterpret_cast<const float4*>(w) + (size_t)b * 4;
    float4 t0 = src[0], t1 = src[1], t2 = src[2], t3 = src[3];
    float v[16] = {t0.x, t0.y, t0.z, t0.w, t1.x, t1.y, t1.z, t1.w,
                   t2.x, t2.y, t2.z, t2.w, t3.x, t3.y, t3.z, t3.w};
    float q[16];
    quant16f(v, q);
#pragma unroll
    for (int i = 0; i < 16; ++i) {
        int f  = b * 16 + i;                // OIHW flat: ((k*256 + c)*9 + rs)
        int k  = f / 2304;
        int r2 = f - k * 2304;
        int c  = r2 / 9;
        int rs = r2 - c * 9;
        wq2[((size_t)rs * K_OUT + k) * C_IN + c] = __float2half(q[i]);
    }
}

// ---------------- PTX helpers ----------------
__device__ __forceinline__ void cp_async16(void* dst, const void* src, bool pred) {
    uint32_t d = (uint32_t)__cvta_generic_to_shared(dst);
    int sz = pred ? 16 : 0;
    asm volatile("cp.async.cg.shared.global [%0], [%1], 16, %2;\n"
                 :: "r"(d), "l"(src), "r"(sz));
}
__device__ __forceinline__ void cp_commit() {
    asm volatile("cp.async.commit_group;\n");
}
template <int N>
__device__ __forceinline__ void cp_wait() {
    asm volatile("cp.async.wait_group %0;\n" :: "n"(N));
}
__device__ __forceinline__ void ldsm_x4(uint32_t addr, uint32_t& r0, uint32_t& r1,
                                        uint32_t& r2, uint32_t& r3) {
    asm volatile("ldmatrix.sync.aligned.m8n8.x4.shared.b16 {%0,%1,%2,%3}, [%4];"
                 : "=r"(r0), "=r"(r1), "=r"(r2), "=r"(r3) : "r"(addr));
}
__device__ __forceinline__ void ldsm_x2(uint32_t addr, uint32_t& r0, uint32_t& r1) {
    asm volatile("ldmatrix.sync.aligned.m8n8.x2.shared.b16 {%0,%1}, [%2];"
                 : "=r"(r0), "=r"(r1) : "r"(addr));
}
// f16 accumulators: d/c are 2 b32 regs (4 halves: n0,n1 | n2,n3 per lane)
__device__ __forceinline__ void mma16816h(uint32_t* d, const uint32_t* a,
                                          uint32_t b0, uint32_t b1) {
    asm volatile("mma.sync.aligned.m16n8k16.row.col.f16.f16.f16.f16 "
                 "{%0,%1}, {%2,%3,%4,%5}, {%6,%7}, {%0,%1};"
                 : "+r"(d[0]), "+r"(d[1])
                 : "r"(a[0]), "r"(a[1]), "r"(a[2]), "r"(a[3]), "r"(b0), "r"(b1));
}

// ---------------- conv: implicit GEMM, f16-acc mma, padded smem ----------------
// CTA: 128 kout x (4 rows x 64 cols). 8 warps: wm(2 k-halves of 64) x wn(4 rows).
// smem rows padded to 24 halves (48B) -> conflict-free ldmatrix. (Round-3 proven.)
#define CPAD 24
#define XS_ELEMS (6 * 66 * CPAD)        // 9504
#define WS_ELEMS (9 * 128 * CPAD)       // 27648
#define SBUF     (XS_ELEMS + WS_ELEMS)  // 37152
#define SMEM_BYTES (2 * SBUF * 2)       // 148608

__device__ __forceinline__ void stage_chunk(__half* xsb, __half* wsb,
                                            const __half* __restrict__ xq,
                                            const __half* __restrict__ wq2,
                                            int n, int h0, int k0, int cc, int t) {
#pragma unroll
    for (int i = 0; i < 3; ++i) {
        int idx  = t + 256 * i;
        int pair = idx >> 1;
        int half = idx & 1;
        int row  = pair >> 6;
        int col  = pair & 63;
        int gr   = h0 - 1 + row;
        bool ok  = (unsigned)gr < (unsigned)HW;
        int grc  = ok ? gr : 0;
        cp_async16(&xsb[(row * 66 + 1 + col) * CPAD + half * 8],
                   xq + (((size_t)n * HW + grc) * HW + col) * C_IN + cc + half * 8, ok);
    }
#pragma unroll
    for (int i = 0; i < 9; ++i) {
        int idx  = t + 256 * i;
        int pair = idx >> 1;
        int half = idx & 1;
        int rs   = pair >> 7;
        int k    = pair & 127;
        cp_async16(&wsb[(rs * 128 + k) * CPAD + half * 8],
                   wq2 + ((size_t)rs * K_OUT + k0 + k) * C_IN + cc + half * 8, true);
    }
}

__global__ void __launch_bounds__(256, 1)
conv3x3_kernel(const __half* __restrict__ xq,
               const __half* __restrict__ wq2,
               float* __restrict__ out) {
    extern __shared__ __half smem[];

    const int n  = blockIdx.x;
    const int ht = blockIdx.y;     // 0..15
    const int kt = blockIdx.z;     // 0..1
    const int h0 = ht * 4;
    const int k0 = kt * 128;

    const int t    = threadIdx.x;
    const int lane = t & 31;
    const int warp = t >> 5;
    const int wm   = warp & 1;     // k half (64 k)
    const int wn   = warp >> 1;    // output row 0..3

    // zero left/right halo columns in both buffers
    if (t < 24) {
        int buf = t / 12;
        int rr  = (t % 12) >> 1;
        int col = (t & 1) ? 65 : 0;
        uint4* p = reinterpret_cast<uint4*>(&smem[buf * SBUF + (rr * 66 + col) * CPAD]);
        p[0] = make_uint4(0, 0, 0, 0);
        p[1] = make_uint4(0, 0, 0, 0);
    }

    // ldmatrix per-lane offsets (in half elements)
    const int a_off = (lane & 15) * CPAD + (lane >> 4) * 8;          // A x4
    const int b_off = (lane & 7) * CPAD + ((lane >> 3) & 1) * 8;     // B x2

    float accf[4][8][4];
#pragma unroll
    for (int i = 0; i < 4; ++i)
#pragma unroll
        for (int j = 0; j < 8; ++j)
#pragma unroll
            for (int v = 0; v < 4; ++v) accf[i][j][v] = 0.0f;

    stage_chunk(smem, smem + XS_ELEMS, xq, wq2, n, h0, k0, 0, t);
    cp_commit();

    const uint32_t smem_u32 = (uint32_t)__cvta_generic_to_shared(smem);

#pragma unroll 1
    for (int it = 0; it < 16; ++it) {
        int cur = it & 1;
        if (it + 1 < 16) {
            int nxt = (it + 1) & 1;
            stage_chunk(smem + nxt * SBUF, smem + nxt * SBUF + XS_ELEMS,
                        xq, wq2, n, h0, k0, (it + 1) * 16, t);
            cp_commit();
            cp_wait<1>();
        } else {
            cp_wait<0>();
        }
        __syncthreads();

        const uint32_t xs_b = smem_u32 + (cur * SBUF) * 2;
        const uint32_t ws_b = xs_b + XS_ELEMS * 2;

        // per-chunk fp16 accumulators (9 adds max before promotion)
        uint32_t acc2[4][8][2];
#pragma unroll
        for (int i = 0; i < 4; ++i)
#pragma unroll
            for (int j = 0; j < 8; ++j) {
                acc2[i][j][0] = 0u;
                acc2[i][j][1] = 0u;
            }

#pragma unroll
        for (int r = 0; r < 3; ++r) {
#pragma unroll
            for (int s = 0; s < 3; ++s) {
                const int rs = r * 3 + s;
                uint32_t a[4][4];
#pragma unroll
                for (int i = 0; i < 4; ++i) {
                    uint32_t addr = ws_b +
                        ((rs * 128 + wm * 64 + i * 16) * CPAD + a_off) * 2;
                    ldsm_x4(addr, a[i][0], a[i][1], a[i][2], a[i][3]);
                }
#pragma unroll
                for (int jn = 0; jn < 8; ++jn) {
                    uint32_t baddr = xs_b +
                        (((wn + r) * 66 + jn * 8 + s) * CPAD + b_off) * 2;
                    uint32_t b0, b1;
                    ldsm_x2(baddr, b0, b1);
#pragma unroll
                    for (int i = 0; i < 4; ++i)
                        mma16816h(acc2[i][jn], a[i], b0, b1);
                }
            }
        }
        // promote chunk partials into fp32 accumulators
#pragma unroll
        for (int i = 0; i < 4; ++i)
#pragma unroll
            for (int j = 0; j < 8; ++j) {
                float2 f0 = __half22float2(*reinterpret_cast<__half2*>(&acc2[i][j][0]));
                float2 f1 = __half22float2(*reinterpret_cast<__half2*>(&acc2[i][j][1]));
                accf[i][j][0] += f0.x;
                accf[i][j][1] += f0.y;
                accf[i][j][2] += f1.x;
                accf[i][j][3] += f1.y;
            }
        __syncthreads();
    }

    // epilogue: lane g=lane/4 holds cols 2t,2t+1 at rows g, g+8
    const int g  = lane >> 2;
    const int tc = lane & 3;
    const size_t kbase = (size_t)n * K_OUT + k0 + wm * 64;
#pragma unroll
    for (int i = 0; i < 4; ++i) {
#pragma unroll
        for (int jn = 0; jn < 8; ++jn) {
            size_t o0 = ((kbase + i * 16 + g) * HW + h0 + wn) * HW + jn * 8 + 2 * tc;
            size_t o1 = o0 + (size_t)8 * HW * HW;
            *reinterpret_cast<float2*>(out + o0) = make_float2(accf[i][jn][0], accf[i][jn][1]);
            *reinterpret_cast<float2*>(out + o1) = make_float2(accf[i][jn][2], accf[i][jn][3]);
        }
    }
}

// ---------------- launch ----------------
extern "C" void kernel_launch(void* const* d_in, const int* in_sizes, int n_in,
                              void* d_out, int out_size) {
    const float* x = (const float*)d_in[0];
    const float* w = (const float*)d_in[1];
    if (in_sizes[0] != X_ELEMS) {
        x = (const float*)d_in[1];
        w = (const float*)d_in[0];
    }

    void* xq_ptr = nullptr;
    void* wq_ptr = nullptr;
    cudaGetSymbolAddress(&xq_ptr, g_xq);
    cudaGetSymbolAddress(&wq_ptr, g_wq2);
    __half* xq  = (__half*)xq_ptr;
    __half* wq2 = (__half*)wq_ptr;

    cudaFuncSetAttribute(conv3x3_kernel,
                         cudaFuncAttributeMaxDynamicSharedMemorySize, SMEM_BYTES);

    quant_x_nhwc<<<dim3(N_IMG, HW), 256>>>(x, xq);
    quant_w_repack<<<(NWBLK + 255) / 256, 256>>>(w, wq2);

    dim3 grid(N_IMG, 16, 2);
    conv3x3_kernel<<<grid, 256, SMEM_BYTES>>>(xq, wq2, (float*)d_out);
}